// round 4
// baseline (speedup 1.0000x reference)
#include <cuda_runtime.h>

// Problem constants
#define NB    8
#define NP    2048
#define BN    (NB * NP)
#define ITERS 50
#define NWARP 8                  // j-split warps per 32-row group
#define JCH   (NP / NWARP)       // 256 j's per warp

// eps = 0.005
#define SF      288.5390081777927f    // 1/(eps*ln2)
#define TWOSF   577.0780163555854f    // 2/(eps*ln2)
#define EPSLN2  0.0034657359027997264f
#define LOG2NF  11.0f

typedef unsigned long long ULL;

// SoA global state. h = s*(pot - |p|^2), s = 1/(eps ln2).
__device__ float g_x1[BN], g_y1[BN], g_z1[BN], g_s1[BN], g_h1[BN];
__device__ float g_x2[BN], g_y2[BN], g_z2[BN], g_s2[BN], g_h2[BN];
__device__ float g_part[BN / 32];

// ---------------- scalar helpers ----------------
__device__ __forceinline__ float ex2f(float x) {
    float r; asm("ex2.approx.ftz.f32 %0, %1;" : "=f"(r) : "f"(x)); return r;
}
__device__ __forceinline__ float lg2f(float x) {
    float r; asm("lg2.approx.ftz.f32 %0, %1;" : "=f"(r) : "f"(x)); return r;
}

// ---------------- packed f32x2 helpers ----------------
__device__ __forceinline__ ULL pack2(float lo, float hi) {
    ULL r; asm("mov.b64 %0, {%1, %2};" : "=l"(r) : "f"(lo), "f"(hi)); return r;
}
__device__ __forceinline__ void unpack2(ULL v, float& lo, float& hi) {
    asm("mov.b64 {%0, %1}, %2;" : "=f"(lo), "=f"(hi) : "l"(v));
}
__device__ __forceinline__ ULL fma2(ULL a, ULL b, ULL c) {
    ULL r; asm("fma.rn.f32x2 %0, %1, %2, %3;" : "=l"(r) : "l"(a), "l"(b), "l"(c)); return r;
}
__device__ __forceinline__ ULL add2(ULL a, ULL b) {
    ULL r; asm("add.rn.f32x2 %0, %1, %2;" : "=l"(r) : "l"(a), "l"(b)); return r;
}
__device__ __forceinline__ ULL sub2(ULL a, ULL b) {
    ULL r; asm("sub.rn.f32x2 %0, %1, %2;" : "=l"(r) : "l"(a), "l"(b)); return r;
}
__device__ __forceinline__ ULL mul2(ULL a, ULL b) {
    ULL r; asm("mul.rn.f32x2 %0, %1, %2;" : "=l"(r) : "l"(a), "l"(b)); return r;
}
// 16B shared load -> two packed pairs
__device__ __forceinline__ void lds4(const float* sp, ULL& a, ULL& b) {
    unsigned addr = (unsigned)__cvta_generic_to_shared(sp);
    asm volatile("ld.shared.v2.b64 {%0, %1}, [%2];" : "=l"(a), "=l"(b) : "r"(addr));
}

// ---------------------------------------------------------------------------
__global__ void init_k(const float* __restrict__ pc1, const float* __restrict__ pc2) {
    int idx = blockIdx.x * blockDim.x + threadIdx.x;
    if (idx >= BN) return;

    float x = pc1[3 * idx + 0], y = pc1[3 * idx + 1], z = pc1[3 * idx + 2];
    float sq = x * x + y * y + z * z;
    g_x1[idx] = x; g_y1[idx] = y; g_z1[idx] = z; g_s1[idx] = sq;
    g_h1[idx] = -SF * sq;

    x = pc2[3 * idx + 0]; y = pc2[3 * idx + 1]; z = pc2[3 * idx + 2];
    sq = x * x + y * y + z * z;
    g_x2[idx] = x; g_y2[idx] = y; g_z2[idx] = z; g_s2[idx] = sq;
    g_h2[idx] = -SF * sq;
}

// ---------------------------------------------------------------------------
// Half-step: A_j = (2s p_i).q_j + h_j ; h_out_i = -log2N - LSE2_j(A_j).
// Block = 8 warps; lane = row; warp w covers j-chunk w. j-side staged in smem
// SoA; inner loop = packed f32x2 (2 j per op), scalar ex2.
// ---------------------------------------------------------------------------
__global__ void __launch_bounds__(32 * NWARP, 4) upd_k(int dir) {
    const float* __restrict__ ix = dir ? g_x2 : g_x1;
    const float* __restrict__ iy = dir ? g_y2 : g_y1;
    const float* __restrict__ iz = dir ? g_z2 : g_z1;
    const float* __restrict__ jx = dir ? g_x1 : g_x2;
    const float* __restrict__ jy = dir ? g_y1 : g_y2;
    const float* __restrict__ jz = dir ? g_z1 : g_z2;
    const float* __restrict__ jh = dir ? g_h1 : g_h2;
    float*       __restrict__ ho = dir ? g_h2 : g_h1;

    __shared__ __align__(16) float sx[NP], sy[NP], sz[NP], sh[NP];
    __shared__ float msh[NWARP][32];
    __shared__ float ssh[NWARP][32];

    int lane = threadIdx.x & 31;
    int w    = threadIdx.x >> 5;
    int blk  = blockIdx.x;
    int b    = blk >> 6;
    int i    = ((blk & 63) << 5) + lane;
    int base = b * NP;
    int b4   = base >> 2;

    // Stage j-side (SoA, float4-coalesced)
    #pragma unroll
    for (int t = 0; t < NP / 4 / (32 * NWARP); t++) {
        int idx = t * 32 * NWARP + threadIdx.x;
        ((float4*)sx)[idx] = __ldg((const float4*)jx + b4 + idx);
        ((float4*)sy)[idx] = __ldg((const float4*)jy + b4 + idx);
        ((float4*)sz)[idx] = __ldg((const float4*)jz + b4 + idx);
        ((float4*)sh)[idx] = __ldg((const float4*)jh + b4 + idx);
    }

    float px = TWOSF * __ldg(ix + base + i);
    float py = TWOSF * __ldg(iy + base + i);
    float pz = TWOSF * __ldg(iz + base + i);
    __syncthreads();

    const float* qx = sx + w * JCH;
    const float* qy = sy + w * JCH;
    const float* qz = sz + w * JCH;
    const float* qh = sh + w * JCH;

    ULL px2 = pack2(px, px), py2 = pack2(py, py), pz2 = pack2(pz, pz);

    // init running max from element 0 (avoid -1e30 absorption)
    float m = fmaf(px, qx[0], fmaf(py, qy[0], fmaf(pz, qz[0], qh[0])));
    ULL mneg2 = pack2(-m, -m);
    ULL s01 = 0ULL, s23 = 0ULL;   // packed {0,0}

    #pragma unroll 2
    for (int j = 0; j < JCH; j += 4) {
        ULL x01, x23, y01, y23, z01, z23, h01, h23;
        lds4(qx + j, x01, x23);
        lds4(qy + j, y01, y23);
        lds4(qz + j, z01, z23);
        lds4(qh + j, h01, h23);

        ULL A01 = fma2(px2, x01, fma2(py2, y01, fma2(pz2, z01, h01)));
        ULL A23 = fma2(px2, x23, fma2(py2, y23, fma2(pz2, z23, h23)));
        ULL B01 = add2(A01, mneg2);
        ULL B23 = add2(A23, mneg2);

        float a0, a1, a2, a3;
        unpack2(B01, a0, a1);
        unpack2(B23, a2, a3);
        float c = fmaxf(fmaxf(a0, a1), fmaxf(a2, a3));

        if (c > 0.0f) {                 // rare: new running max
            float sc = ex2f(-c);
            ULL sc2 = pack2(sc, sc);
            s01 = mul2(s01, sc2);
            s23 = mul2(s23, sc2);
            m += c;
            mneg2 = pack2(-m, -m);
            a0 -= c; a1 -= c; a2 -= c; a3 -= c;
        }

        s01 = add2(s01, pack2(ex2f(a0), ex2f(a1)));
        s23 = add2(s23, pack2(ex2f(a2), ex2f(a3)));
    }

    float s0, s1, s2, s3;
    unpack2(s01, s0, s1);
    unpack2(s23, s2, s3);
    float s = (s0 + s1) + (s2 + s3);

    msh[w][lane] = m;
    ssh[w][lane] = s;
    __syncthreads();

    if (w == 0) {
        float M = msh[0][lane];
        #pragma unroll
        for (int k = 1; k < NWARP; k++) M = fmaxf(M, msh[k][lane]);
        float S = 0.f;
        #pragma unroll
        for (int k = 0; k < NWARP; k++) S += ssh[k][lane] * ex2f(msh[k][lane] - M);
        ho[base + i] = -LOG2NF - M - lg2f(S);
    }
}

// ---------------------------------------------------------------------------
// dist_i = N * sum_j exp2(h1_i + A_j) * C_ij ; C = s1 + s2_j - (A - h_j)*eps*ln2
// Packed variant; exponents <= ~-log2N so plain sums are safe.
// ---------------------------------------------------------------------------
__global__ void __launch_bounds__(32 * NWARP, 4) dist_k() {
    __shared__ __align__(16) float sx[NP], sy[NP], sz[NP], sh[NP], ss[NP];
    __shared__ float ash[NWARP][32];

    int lane = threadIdx.x & 31;
    int w    = threadIdx.x >> 5;
    int blk  = blockIdx.x;
    int b    = blk >> 6;
    int i    = ((blk & 63) << 5) + lane;
    int base = b * NP;
    int b4   = base >> 2;

    #pragma unroll
    for (int t = 0; t < NP / 4 / (32 * NWARP); t++) {
        int idx = t * 32 * NWARP + threadIdx.x;
        ((float4*)sx)[idx] = __ldg((const float4*)g_x2 + b4 + idx);
        ((float4*)sy)[idx] = __ldg((const float4*)g_y2 + b4 + idx);
        ((float4*)sz)[idx] = __ldg((const float4*)g_z2 + b4 + idx);
        ((float4*)sh)[idx] = __ldg((const float4*)g_h2 + b4 + idx);
        ((float4*)ss)[idx] = __ldg((const float4*)g_s2 + b4 + idx);
    }

    float px = TWOSF * __ldg(g_x1 + base + i);
    float py = TWOSF * __ldg(g_y1 + base + i);
    float pz = TWOSF * __ldg(g_z1 + base + i);
    float sq1 = __ldg(g_s1 + base + i);
    float tf  = __ldg(g_h1 + base + i);
    __syncthreads();

    const float* qx = sx + w * JCH;
    const float* qy = sy + w * JCH;
    const float* qz = sz + w * JCH;
    const float* qh = sh + w * JCH;
    const float* qs = ss + w * JCH;

    ULL px2 = pack2(px, px), py2 = pack2(py, py), pz2 = pack2(pz, pz);
    ULL tf2 = pack2(tf, tf);
    ULL s1p = pack2(sq1, sq1);
    ULL ne2 = pack2(-EPSLN2, -EPSLN2);

    ULL acc01 = 0ULL, acc23 = 0ULL;

    #pragma unroll 2
    for (int j = 0; j < JCH; j += 4) {
        ULL x01, x23, y01, y23, z01, z23, h01, h23, q01, q23;
        lds4(qx + j, x01, x23);
        lds4(qy + j, y01, y23);
        lds4(qz + j, z01, z23);
        lds4(qh + j, h01, h23);
        lds4(qs + j, q01, q23);

        ULL A01 = fma2(px2, x01, fma2(py2, y01, fma2(pz2, z01, h01)));
        ULL A23 = fma2(px2, x23, fma2(py2, y23, fma2(pz2, z23, h23)));

        ULL E01 = add2(A01, tf2);
        ULL E23 = add2(A23, tf2);
        float e0, e1, e2, e3;
        unpack2(E01, e0, e1);
        unpack2(E23, e2, e3);
        ULL P01 = pack2(ex2f(e0), ex2f(e1));
        ULL P23 = pack2(ex2f(e2), ex2f(e3));

        ULL C01 = fma2(sub2(A01, h01), ne2, add2(s1p, q01));
        ULL C23 = fma2(sub2(A23, h23), ne2, add2(s1p, q23));

        acc01 = fma2(P01, C01, acc01);
        acc23 = fma2(P23, C23, acc23);
    }

    float a0, a1, a2, a3;
    unpack2(acc01, a0, a1);
    unpack2(acc23, a2, a3);
    float acc = (a0 + a1) + (a2 + a3);

    ash[w][lane] = acc;
    __syncthreads();

    if (w == 0) {
        float S = ash[0][lane];
        #pragma unroll
        for (int k = 1; k < NWARP; k++) S += ash[k][lane];
        float v = sqrtf((float)NP * S + 1e-12f);
        #pragma unroll
        for (int o = 16; o; o >>= 1) v += __shfl_xor_sync(0xffffffffu, v, o);
        if (lane == 0) g_part[blk] = v;
    }
}

// ---------------------------------------------------------------------------
__global__ void finish_k(float* __restrict__ out) {
    __shared__ float sh[BN / 32];
    int t = threadIdx.x;
    sh[t] = g_part[t];
    __syncthreads();
    for (int s = (BN / 32) / 2; s > 0; s >>= 1) {
        if (t < s) sh[t] += sh[t + s];
        __syncthreads();
    }
    if (t == 0) out[0] = sh[0] * (1.0f / (float)BN);
}

// ---------------------------------------------------------------------------
extern "C" void kernel_launch(void* const* d_in, const int* in_sizes, int n_in,
                              void* d_out, int out_size) {
    const float* pc1 = (const float*)d_in[0];
    const float* pc2 = (const float*)d_in[1];
    float* out = (float*)d_out;

    init_k<<<(BN + 255) / 256, 256>>>(pc1, pc2);

    for (int it = 0; it < ITERS; it++) {
        upd_k<<<BN / 32, 32 * NWARP>>>(0);   // f-update: reads h2, writes h1
        upd_k<<<BN / 32, 32 * NWARP>>>(1);   // g-update: reads h1, writes h2
    }

    dist_k<<<BN / 32, 32 * NWARP>>>();
    finish_k<<<1, BN / 32>>>(out);

    (void)in_sizes; (void)n_in; (void)out_size;
}